// round 1
// baseline (speedup 1.0000x reference)
#include <cuda_runtime.h>

// Problem constants (fixed by the dataset)
//   B=131072, IN_DIM=128, N_NODES=511, N_LEAVES=512, N_ACTIONS=16
#define TM        32                    // rows per block
#define KS        8                     // node (k) slice per W2 stage
#define WS_STRIDE 516                   // padded leaf-stride (mult of 4, bank-skewed)
#define WS_HALF   (KS * WS_STRIDE)      // 4128 floats per half
#define HT_FLOATS (512 * TM)            // 16384 floats (node 511 zero-padded)
#define POOL_OFF  (HT_FLOATS + 2 * WS_HALF)   // 24640
#define SMEM_FLOATS (POOL_OFF + TM * 16)      // 25152
#define SMEM_BYTES  (SMEM_FLOATS * 4)         // 100608 B -> 2 CTAs/SM

// order-preserving float<->uint for atomicMax-based segment max
__device__ __forceinline__ unsigned ford(float f) {
    unsigned u = __float_as_uint(f);
    return (u & 0x80000000u) ? ~u : (u | 0x80000000u);
}
__device__ __forceinline__ float funord(unsigned s) {
    return __uint_as_float((s & 0x80000000u) ? (s ^ 0x80000000u) : ~s);
}

__global__ __launch_bounds__(256, 2)
void dtnet_fused_kernel(const float* __restrict__ x,
                        const float* __restrict__ W1,
                        const float* __restrict__ b1,
                        const float* __restrict__ W2,
                        const int*   __restrict__ leaf_actions,
                        float*       __restrict__ out)
{
    extern __shared__ float sm[];
    float*    ht   = sm;                          // [512 nodes][32 rows]
    float*    ws   = sm + HT_FLOATS;              // staged W2 slice (2 halves)
    unsigned* pool = (unsigned*)(sm + POOL_OFF);  // [32 rows][16 actions]
    float*    xs   = ws;                          // phase-1 scratch (128*33 = 4224 <= 8256)

    const int tid  = threadIdx.x;
    const int row0 = blockIdx.x * TM;

    // ---- init action-max pool (ford encoding: 0 < ord(-inf), so 0 is safe bottom)
    for (int i = tid; i < TM * 16; i += 256) pool[i] = 0u;

    // ---- stage x tile transposed: xs[k*33 + r]
    {
        const float4* xg = (const float4*)(x + (size_t)row0 * 128);
        for (int i = tid; i < TM * 32; i += 256) {
            int r  = i >> 5;
            int k4 = i & 31;
            float4 v = xg[r * 32 + k4];
            int k = k4 * 4;
            xs[(k + 0) * 33 + r] = v.x;
            xs[(k + 1) * 33 + r] = v.y;
            xs[(k + 2) * 33 + r] = v.z;
            xs[(k + 3) * 33 + r] = v.w;
        }
    }
    __syncthreads();

    // ---- phase 1: ht[n][r] = x[r] . W1[n] + b1[n]   (4n x 4r register tile)
    const float4* w1v = (const float4*)W1;
    for (int it = 0; it < 4; it++) {
        int idx = it * 256 + tid;      // 0..1023
        int ng  = idx >> 3;            // 0..127  (node group of 4)
        int rq  = idx & 7;             // row group of 4
        float acc1[4][4];
        #pragma unroll
        for (int i = 0; i < 4; i++) {
            int n = ng * 4 + i;
            float bb = b1[n < 511 ? n : 510];
            #pragma unroll
            for (int j = 0; j < 4; j++) acc1[i][j] = bb;
        }
        #pragma unroll 4
        for (int k4 = 0; k4 < 32; k4++) {
            float4 w[4];
            #pragma unroll
            for (int i = 0; i < 4; i++) {
                int n = ng * 4 + i; if (n > 510) n = 510;
                w[i] = w1v[(size_t)n * 32 + k4];
            }
            float xv[4][4];
            #pragma unroll
            for (int kk = 0; kk < 4; kk++)
                #pragma unroll
                for (int j = 0; j < 4; j++)
                    xv[kk][j] = xs[(k4 * 4 + kk) * 33 + rq * 4 + j];
            #pragma unroll
            for (int i = 0; i < 4; i++)
                #pragma unroll
                for (int j = 0; j < 4; j++) {
                    acc1[i][j] = fmaf(w[i].x, xv[0][j], acc1[i][j]);
                    acc1[i][j] = fmaf(w[i].y, xv[1][j], acc1[i][j]);
                    acc1[i][j] = fmaf(w[i].z, xv[2][j], acc1[i][j]);
                    acc1[i][j] = fmaf(w[i].w, xv[3][j], acc1[i][j]);
                }
        }
        #pragma unroll
        for (int i = 0; i < 4; i++) {
            int n = ng * 4 + i;
            if (n < 511) {
                #pragma unroll
                for (int j = 0; j < 4; j++)
                    ht[n * TM + rq * 4 + j] = acc1[i][j];
            }
        }
    }
    if (tid < TM) ht[511 * TM + tid] = 0.0f;   // zero-pad node 511

    // ---- phase 2: y[r][l] = sum_j relu(h[r][j])*W2[l][j] + relu(-h[r][j])*W2[l][511+j]
    const int rg = tid >> 6;   // 0..3  -> rows rg*8..rg*8+7
    const int cg = tid & 63;   // 0..63 -> leaves cg*8..cg*8+7
    float acc[8][8];
    #pragma unroll
    for (int r = 0; r < 8; r++)
        #pragma unroll
        for (int c = 0; c < 8; c++) acc[r][c] = 0.0f;

    for (int j0 = 0; j0 < 512; j0 += KS) {
        __syncthreads();
        // stage W2 slice: j-fast mapping -> coalesced LDG, bank-skewed STS
        for (int i = tid; i < KS * 512; i += 256) {
            int l  = i >> 3;
            int jj = i & 7;
            int j  = j0 + jj;                         // 0..511 (j=511 is zero-padded node)
            int jb = 511 + (j < 511 ? j : 510);       // clamp avoids OOB; multiplied by 0
            ws[jj * WS_STRIDE + l]           = W2[(size_t)l * 1022 + j];
            ws[WS_HALF + jj * WS_STRIDE + l] = W2[(size_t)l * 1022 + jb];
        }
        __syncthreads();

        #pragma unroll
        for (int jj = 0; jj < KS; jj++) {
            int j = j0 + jj;
            const float4* ap = (const float4*)(ht + j * TM + rg * 8);
            float4 a0 = ap[0], a1 = ap[1];
            float p[8], m[8];
            p[0] = fmaxf(a0.x, 0.f); m[0] = fmaxf(-a0.x, 0.f);
            p[1] = fmaxf(a0.y, 0.f); m[1] = fmaxf(-a0.y, 0.f);
            p[2] = fmaxf(a0.z, 0.f); m[2] = fmaxf(-a0.z, 0.f);
            p[3] = fmaxf(a0.w, 0.f); m[3] = fmaxf(-a0.w, 0.f);
            p[4] = fmaxf(a1.x, 0.f); m[4] = fmaxf(-a1.x, 0.f);
            p[5] = fmaxf(a1.y, 0.f); m[5] = fmaxf(-a1.y, 0.f);
            p[6] = fmaxf(a1.z, 0.f); m[6] = fmaxf(-a1.z, 0.f);
            p[7] = fmaxf(a1.w, 0.f); m[7] = fmaxf(-a1.w, 0.f);

            const float4* bap = (const float4*)(ws + jj * WS_STRIDE + cg * 8);
            const float4* bbp = (const float4*)(ws + WS_HALF + jj * WS_STRIDE + cg * 8);
            float4 ba0 = bap[0], ba1 = bap[1];
            float4 bb0 = bbp[0], bb1 = bbp[1];
            float ba[8] = {ba0.x, ba0.y, ba0.z, ba0.w, ba1.x, ba1.y, ba1.z, ba1.w};
            float bb[8] = {bb0.x, bb0.y, bb0.z, bb0.w, bb1.x, bb1.y, bb1.z, bb1.w};

            #pragma unroll
            for (int r = 0; r < 8; r++)
                #pragma unroll
                for (int c = 0; c < 8; c++)
                    acc[r][c] = fmaf(p[r], ba[c], fmaf(m[r], bb[c], acc[r][c]));
        }
    }

    // ---- phase 3: grouped segment-max via shared atomicMax on ordered uints
    #pragma unroll
    for (int c = 0; c < 8; c++) {
        int l = cg * 8 + c;
        int a = leaf_actions[l] & 15;
        #pragma unroll
        for (int r = 0; r < 8; r++)
            atomicMax(&pool[(rg * 8 + r) * 16 + a], ford(acc[r][c]));
    }
    __syncthreads();

    // ---- softmax over 16 actions, one thread per row
    if (tid < TM) {
        float v[16];
        float mx = -3.402823466e38f;
        #pragma unroll
        for (int a = 0; a < 16; a++) {
            v[a] = funord(pool[tid * 16 + a]);
            mx = fmaxf(mx, v[a]);
        }
        float s = 0.f;
        #pragma unroll
        for (int a = 0; a < 16; a++) { v[a] = __expf(v[a] - mx); s += v[a]; }
        float inv = 1.f / s;
        float4* o = (float4*)(out + (size_t)(row0 + tid) * 16);
        o[0] = make_float4(v[0] * inv,  v[1] * inv,  v[2] * inv,  v[3] * inv);
        o[1] = make_float4(v[4] * inv,  v[5] * inv,  v[6] * inv,  v[7] * inv);
        o[2] = make_float4(v[8] * inv,  v[9] * inv,  v[10] * inv, v[11] * inv);
        o[3] = make_float4(v[12] * inv, v[13] * inv, v[14] * inv, v[15] * inv);
    }
}

extern "C" void kernel_launch(void* const* d_in, const int* in_sizes, int n_in,
                              void* d_out, int out_size)
{
    const float* x  = (const float*)d_in[0];
    const float* W1 = (const float*)d_in[1];
    const float* b1 = (const float*)d_in[2];
    const float* W2 = (const float*)d_in[3];
    const int*   la = (const int*)d_in[4];
    float* out = (float*)d_out;

    int Btot = in_sizes[0] / 128;          // 131072
    cudaFuncSetAttribute(dtnet_fused_kernel,
                         cudaFuncAttributeMaxDynamicSharedMemorySize, SMEM_BYTES);
    dtnet_fused_kernel<<<Btot / TM, 256, SMEM_BYTES>>>(x, W1, b1, W2, la, out);
}